// round 12
// baseline (speedup 1.0000x reference)
#include <cuda_runtime.h>
#include <cstdint>

#define BATCH 256
#define NSRC  10
#define NMC_C 16
#define LL_C  128
#define PLANE (LL_C * LL_C)            // 16384 floats per channel plane
#define TPB   256
#define NBLK  131072                   // 16 blocks per plane, R1-identical geometry

// One block = one 256-float4 (1KB-float) window of one channel plane.
// Warp 0 computes the batch's scatter points while all warps issue their
// single unconditional STG.128; after one barrier, warp 0 applies the
// (rare) overrides that fall inside this block's window.
__global__ void __launch_bounds__(TPB) fused_kernel(
    const float* __restrict__ coord,
    const float* __restrict__ lows,
    const float* __restrict__ highs,
    float* __restrict__ out)
{
    __shared__ int s_off[NSRC];   // in-plane float offset of point t, or -1

    int bid   = blockIdx.x;
    int t     = threadIdx.x;
    int plane = bid >> 4;          // 0..8191
    int w     = bid & 15;          // float4-window within plane (256 f4 each)
    int ch    = plane & 31;        // channel 0..31
    int batch = plane >> 5;
    int bin   = ch & (NMC_C - 1);

    // --- point math on warp 0 only (overlapped with stores below) ---
    if (t < NSRC) {
        const float* c = coord + batch * (3 * NSRC) + t * 3;
        float lo0 = lows[0], lo1 = lows[1], lo2 = lows[2];
        float hi0 = highs[0], hi1 = highs[1], hi2 = highs[2];

        float xg = (c[0]         - lo0) / (hi0 - lo0);
        float yg = (c[1]         - lo1) / (hi1 - lo1);
        float mg = (log10f(c[2]) - lo2) / (hi2 - lo2);

        int xi = (int)floorf(xg * (float)LL_C);
        int yi = (int)floorf(yg * (float)LL_C);
        int mi = (int)floorf(mg * (float)NMC_C);

        bool ok = ((unsigned)xi < LL_C) & ((unsigned)yi < LL_C) &
                  ((unsigned)mi < NMC_C) & (mi == bin);
        s_off[t] = ok ? (yi * LL_C + xi) : -1;
    }

    // --- unconditional streaming store, no dependencies (R1 geometry) ---
    float v = (ch < NMC_C) ? 1.0f : 0.0f;
    ((float4*)out)[(long)bid * TPB + t] = make_float4(v, v, v, v);

    __syncthreads();   // orders intra-block global stores before the patch

    // --- apply overrides landing in this block's window ---
    if (t < NSRC) {
        int o = s_off[t];
        if (o >= 0 && (o >> 10) == w)
            out[(size_t)plane * PLANE + o] = 1.0f - v;
    }
}

extern "C" void kernel_launch(void* const* d_in, const int* in_sizes, int n_in,
                              void* d_out, int out_size) {
    const float* coord = (const float*)d_in[0];
    const float* lows  = (const float*)d_in[1];
    const float* highs = (const float*)d_in[2];
    float* out = (float*)d_out;

    fused_kernel<<<NBLK, TPB>>>(coord, lows, highs, out);
}

// round 13
// speedup vs baseline: 1.3031x; 1.3031x over previous
#include <cuda_runtime.h>
#include <cstdint>

#define BATCH 256
#define NSRC  10
#define NMC_C 16
#define LL_C  128
#define PLANE (LL_C * LL_C)          // 16384 floats per channel plane
#define TPB   256
#define NFILL 131072                 // R1 geometry: 16 blocks per plane
#define NTAB  (BATCH * NMC_C)        // 4096 (batch, bin) table entries

// Override table, fully rebuilt by kernel A every launch (deterministic).
// Word for (batch, bin):
//   -1                         : no override in this plane-pair
//   [0, 16384)                 : single override, in-plane float offset
//   positive, bit30 set        : two overrides: o1 = w & 0x3FFF, o2 = (w>>14) & 0x3FFF
//   negative, != -1            : cnt = w & 0xFF overrides in g_aux[tidx*NSRC + j]
__device__ int g_tab[NTAB];
__device__ int g_aux[NTAB * NSRC];

// ---------------------------------------------------------------------------
// Kernel A: one thread per (batch, bin). ~2us; all the log10/index math
// in the whole job happens here, once.
// ---------------------------------------------------------------------------
__global__ void __launch_bounds__(TPB) table_kernel(
    const float* __restrict__ coord,
    const float* __restrict__ lows,
    const float* __restrict__ highs)
{
    int gid = blockIdx.x * TPB + threadIdx.x;
    if (gid >= NTAB) return;
    int b   = gid >> 4;
    int bin = gid & 15;

    float lo0 = lows[0], lo1 = lows[1], lo2 = lows[2];
    float hi0 = highs[0], hi1 = highs[1], hi2 = highs[2];

    int offs[NSRC];
    int cnt = 0;
#pragma unroll
    for (int s = 0; s < NSRC; s++) {
        const float* c = coord + (size_t)b * (3 * NSRC) + s * 3;
        float xg = (c[0]         - lo0) / (hi0 - lo0);
        float yg = (c[1]         - lo1) / (hi1 - lo1);
        float mg = (log10f(c[2]) - lo2) / (hi2 - lo2);

        int xi = (int)floorf(xg * (float)LL_C);
        int yi = (int)floorf(yg * (float)LL_C);
        int mi = (int)floorf(mg * (float)NMC_C);

        bool ok = ((unsigned)xi < LL_C) & ((unsigned)yi < LL_C) &
                  ((unsigned)mi < NMC_C) & (mi == bin);
        if (ok) offs[cnt++] = yi * LL_C + xi;
    }

    int w;
    if (cnt == 0)      w = -1;
    else if (cnt == 1) w = offs[0];
    else if (cnt == 2) w = (1 << 30) | (offs[1] << 14) | offs[0];
    else {
        w = (int)(0x80000000u | (unsigned)cnt);
        for (int j = 0; j < cnt; j++) g_aux[gid * NSRC + j] = offs[j];
    }
    g_tab[gid] = w;
}

// ---------------------------------------------------------------------------
// Kernel B: exact R1 fill geometry (one unconditional STG.128 per thread),
// plus a near-free thread-0 patch of this block's 1K-float window.
// The table LDG is issued before the store (latency hidden); patch stores
// hit the block's own just-written L2 lines.
// ---------------------------------------------------------------------------
__global__ void __launch_bounds__(TPB) fill_patch_kernel(
    float* __restrict__ out)
{
    int bid   = blockIdx.x;
    int t     = threadIdx.x;
    int plane = bid >> 4;                 // 0..8191
    int win   = bid & 15;                 // 1K-float window within plane
    int ch    = plane & 31;
    int tidx  = ((plane >> 5) << 4) | (ch & (NMC_C - 1));

    int w = -1;
    if (t == 0) w = __ldg(&g_tab[tidx]);  // issued early, consumed after barrier

    float v = (ch < NMC_C) ? 1.0f : 0.0f;
    ((float4*)out)[(long)bid * TPB + t] = make_float4(v, v, v, v);

    __syncthreads();                      // order intra-block stores before patch

    if (w != -1) {                        // only possibly true for t==0
        float ov = 1.0f - v;
        float* pb = out + (size_t)plane * PLANE;
        if ((unsigned)w < 16384u) {                       // single
            if ((w >> 10) == win) pb[w] = ov;
        } else if (w > 0) {                               // double
            int o1 = w & 0x3FFF, o2 = (w >> 14) & 0x3FFF;
            if ((o1 >> 10) == win) pb[o1] = ov;
            if ((o2 >> 10) == win) pb[o2] = ov;
        } else {                                          // escape list
            int cnt = w & 0xFF;
            const int* a = &g_aux[tidx * NSRC];
            for (int j = 0; j < cnt; j++) {
                int o = __ldg(&a[j]);
                if ((o >> 10) == win) pb[o] = ov;
            }
        }
    }
}

extern "C" void kernel_launch(void* const* d_in, const int* in_sizes, int n_in,
                              void* d_out, int out_size) {
    const float* coord = (const float*)d_in[0];
    const float* lows  = (const float*)d_in[1];
    const float* highs = (const float*)d_in[2];

    table_kernel<<<NTAB / TPB, TPB>>>(coord, lows, highs);
    fill_patch_kernel<<<NFILL, TPB>>>((float*)d_out);
}

// round 14
// speedup vs baseline: 1.4146x; 1.0856x over previous
#include <cuda_runtime.h>
#include <cstdint>

#define BATCH 256
#define NSRC  10
#define NMC_C 16
#define LL_C  128
#define PLANE (LL_C * LL_C)          // 16384 floats per channel plane
#define PLANE4 (PLANE / 4)           // 4096 float4
#define TPB   256
#define NPLANE_BLK (BATCH * 2 * NMC_C)   // 8192 plane blocks
#define NTAB  (BATCH * NMC_C)        // 4096 (batch, bin) table entries

// Override table, fully rebuilt by the table kernel every launch.
// Word for (batch, bin):
//   -1                  : no override
//   [0, 16384)          : single override, in-plane float offset
//   positive, bit30 set : two: o1 = w & 0x3FFF, o2 = (w>>14) & 0x3FFF
//   negative, != -1     : cnt = w & 0xFF offsets in g_aux[tidx*NSRC + j]
__device__ int g_tab[NTAB];
__device__ int g_aux[NTAB * NSRC];

// ---------------------------------------------------------------------------
// Table kernel: one thread per (batch, bin). All scatter math lives here.
// ---------------------------------------------------------------------------
__global__ void __launch_bounds__(TPB) table_kernel(
    const float* __restrict__ coord,
    const float* __restrict__ lows,
    const float* __restrict__ highs)
{
    int gid = blockIdx.x * TPB + threadIdx.x;
    if (gid >= NTAB) return;
    int b   = gid >> 4;
    int bin = gid & 15;

    float lo0 = lows[0], lo1 = lows[1], lo2 = lows[2];
    float hi0 = highs[0], hi1 = highs[1], hi2 = highs[2];

    int offs[NSRC];
    int cnt = 0;
#pragma unroll
    for (int s = 0; s < NSRC; s++) {
        const float* c = coord + (size_t)b * (3 * NSRC) + s * 3;
        float xg = (c[0]         - lo0) / (hi0 - lo0);
        float yg = (c[1]         - lo1) / (hi1 - lo1);
        float mg = (log10f(c[2]) - lo2) / (hi2 - lo2);

        int xi = (int)floorf(xg * (float)LL_C);
        int yi = (int)floorf(yg * (float)LL_C);
        int mi = (int)floorf(mg * (float)NMC_C);

        bool ok = ((unsigned)xi < LL_C) & ((unsigned)yi < LL_C) &
                  ((unsigned)mi < NMC_C) & (mi == bin);
        if (ok) offs[cnt++] = yi * LL_C + xi;
    }

    int w;
    if (cnt == 0)      w = -1;
    else if (cnt == 1) w = offs[0];
    else if (cnt == 2) w = (1 << 30) | (offs[1] << 14) | offs[0];
    else {
        w = (int)(0x80000000u | (unsigned)cnt);
        for (int j = 0; j < cnt; j++) g_aux[gid * NSRC + j] = offs[j];
    }
    g_tab[gid] = w;
}

// ---------------------------------------------------------------------------
// Fill+patch: one block per channel plane (R6 geometry). The single t0
// table LDG is hidden behind the ~4000-cycle store phase; after one
// barrier t0 patches <=2 (rarely <=10) just-written L2 lines.
// ---------------------------------------------------------------------------
__global__ void __launch_bounds__(TPB) fill_patch_kernel(
    float* __restrict__ out)
{
    int plane = blockIdx.x;              // 0..8191
    int t     = threadIdx.x;
    int ch    = plane & 31;
    int tidx  = ((plane >> 5) << 4) | (ch & (NMC_C - 1));

    int w = -1;
    if (t == 0) w = __ldg(&g_tab[tidx]); // latency hidden by store phase

    float v = (ch < NMC_C) ? 1.0f : 0.0f;
    float4 vv = make_float4(v, v, v, v);
    float4* p = (float4*)(out + (size_t)plane * PLANE);
#pragma unroll
    for (int k = 0; k < PLANE4 / TPB; k++)
        p[t + k * TPB] = vv;

    __syncthreads();                     // order intra-block stores before patch

    if (w != -1) {                       // only possibly true for t==0
        float ov = 1.0f - v;
        float* pb = out + (size_t)plane * PLANE;
        if ((unsigned)w < 16384u) {                    // single
            pb[w] = ov;
        } else if (w > 0) {                            // double
            pb[w & 0x3FFF] = ov;
            pb[(w >> 14) & 0x3FFF] = ov;
        } else {                                       // escape list
            int cnt = w & 0xFF;
            const int* a = &g_aux[tidx * NSRC];
            for (int j = 0; j < cnt; j++)
                pb[__ldg(&a[j])] = ov;
        }
    }
}

extern "C" void kernel_launch(void* const* d_in, const int* in_sizes, int n_in,
                              void* d_out, int out_size) {
    const float* coord = (const float*)d_in[0];
    const float* lows  = (const float*)d_in[1];
    const float* highs = (const float*)d_in[2];

    table_kernel<<<NTAB / TPB, TPB>>>(coord, lows, highs);
    fill_patch_kernel<<<NPLANE_BLK, TPB>>>((float*)d_out);
}

// round 16
// speedup vs baseline: 1.5358x; 1.0857x over previous
#include <cuda_runtime.h>
#include <cstdint>

#define BATCH 256
#define NSRC  10
#define NMC_C 16
#define LL_C  128
#define PLANE (LL_C * LL_C)            // 16384 floats per channel plane
#define TPB   256
#define HALF_F4 2048                   // float4 per half-plane (8192 floats)
#define NBLK  (BATCH * 2 * NMC_C * 2)  // 16384 half-plane blocks

// Single fused kernel, half-plane blocks (8 float4 stores per thread).
// Threads 0..9 compute this batch's scatter points into REGISTERS
// (no smem, no atomics), all threads issue 8 unconditional STG.128,
// one barrier, then threads 0..9 patch their own point if it lands in
// this block's half-plane. Patch stores hit just-written L2 lines.
__global__ void __launch_bounds__(TPB) fused_kernel(
    const float* __restrict__ coord,
    const float* __restrict__ lows,
    const float* __restrict__ highs,
    float* __restrict__ out)
{
    int bid   = blockIdx.x;
    int t     = threadIdx.x;
    int plane = bid >> 1;              // 0..8191
    int half  = bid & 1;               // which 8192-float half of the plane
    int ch    = plane & 31;            // channel 0..31
    int batch = plane >> 5;
    int bin   = ch & (NMC_C - 1);

    // --- point math, registers only (warp 0; overlapped with stores) ---
    int off = -1;
    if (t < NSRC) {
        const float* c = coord + batch * (3 * NSRC) + t * 3;
        float lo0 = lows[0], lo1 = lows[1], lo2 = lows[2];
        float hi0 = highs[0], hi1 = highs[1], hi2 = highs[2];

        float xg = (c[0]         - lo0) / (hi0 - lo0);
        float yg = (c[1]         - lo1) / (hi1 - lo1);
        float mg = (log10f(c[2]) - lo2) / (hi2 - lo2);

        int xi = (int)floorf(xg * (float)LL_C);
        int yi = (int)floorf(yg * (float)LL_C);
        int mi = (int)floorf(mg * (float)NMC_C);

        bool ok = ((unsigned)xi < LL_C) & ((unsigned)yi < LL_C) &
                  ((unsigned)mi < NMC_C) & (mi == bin);
        if (ok) off = yi * LL_C + xi;   // in-plane float offset
    }

    // --- unconditional streaming stores: 8 x STG.128 per thread ---
    float v = (ch < NMC_C) ? 1.0f : 0.0f;
    float4 vv = make_float4(v, v, v, v);
    float4* p = (float4*)(out + (size_t)plane * PLANE) + half * HALF_F4;
#pragma unroll
    for (int k = 0; k < HALF_F4 / TPB; k++)    // 8 stores per thread
        p[t + k * TPB] = vv;

    __syncthreads();   // order intra-block global stores before the patch

    // --- register-held patch, only if the point is in this half ---
    if (off >= 0 && (off >> 13) == half)
        out[(size_t)plane * PLANE + off] = 1.0f - v;
}

extern "C" void kernel_launch(void* const* d_in, const int* in_sizes, int n_in,
                              void* d_out, int out_size) {
    const float* coord = (const float*)d_in[0];
    const float* lows  = (const float*)d_in[1];
    const float* highs = (const float*)d_in[2];
    float* out = (float*)d_out;

    fused_kernel<<<NBLK, TPB>>>(coord, lows, highs, out);
}